// round 5
// baseline (speedup 1.0000x reference)
#include <cuda_runtime.h>
#include <cstdint>

// DisulfideEnergy: sulfur-pair energy scatter + fused residue reduction.
//
// Output (single f32 buffer):
//   [0 .. 64000)              resi_energy (8,4,500,4)
//   [64000 .. 2064000)        atom_energy (500000,4)
//   [2064000 .. 6064000)      sulfur      (4000000) as 0.0/1.0

#define N_CHAINS   4
#define N_RES      500
#define SG_CODE    7
#define MAX_ATOMS  500000
#define MAX_WORDS  ((MAX_ATOMS + 31) / 32)   // 15625

__device__ uint32_t g_sgmask[MAX_WORDS + 32];

// ---------------------------------------------------------------------------
// Kernel 1: build SG bitmask. 4 atoms per thread (MLP=4), ballot per chunk.
// ---------------------------------------------------------------------------
__global__ void mask_kernel(const int* __restrict__ desc, int n_atoms)
{
    int base = blockIdx.x * 1024;
    int an[4];
#pragma unroll
    for (int u = 0; u < 4; u++) {
        int a = base + u * 256 + threadIdx.x;
        an[u] = (a < n_atoms) ? __ldcs(desc + 4 * a) : 0;   // at_name column
    }
#pragma unroll
    for (int u = 0; u < 4; u++) {
        int a = base + u * 256 + threadIdx.x;
        unsigned ball = __ballot_sync(0xffffffffu, an[u] == SG_CODE);
        if ((threadIdx.x & 31) == 0 && a < n_atoms)
            g_sgmask[a >> 5] = ball;
    }
}

// ---------------------------------------------------------------------------
// Heavy path: only true sulfur pairs (~1/1600). Updates atomE AND resi.
// ---------------------------------------------------------------------------
__device__ __forceinline__ void heavy_pair(int i, int j,
                                           const float* __restrict__ coords,
                                           const int4* __restrict__ desc4,
                                           const uint32_t* __restrict__ amask,
                                           float* __restrict__ atomE,
                                           float* __restrict__ resi)
{
    float dx = __ldg(coords + 3 * i + 0) - __ldg(coords + 3 * j + 0) + 1e-6f;
    float dy = __ldg(coords + 3 * i + 1) - __ldg(coords + 3 * j + 1) + 1e-6f;
    float dz = __ldg(coords + 3 * i + 2) - __ldg(coords + 3 * j + 2) + 1e-6f;
    float dist = sqrtf(dx * dx + dy * dy + dz * dz);

    int4 di = __ldg(desc4 + i);   // (at_name, resnum, batch, chain)
    int4 dj = __ldg(desc4 + j);

    float rd  = fabsf((float)(di.y - dj.y));
    float rds = (rd > 0.f) ? rd : 1.0f;

    // -0.001*298.0 = -0.298
    float energy = -0.298f * (2.1f + 2.9823825f * logf(rds))
                 + 5.0f * fabsf(dist - 2.04f);
    float net = 0.5f * energy;

    int flat_i = (di.z * N_CHAINS + di.w) * N_RES + di.y;
    int flat_j = (dj.z * N_CHAINS + dj.w) * N_RES + dj.y;

    uint4 mi = *reinterpret_cast<const uint4*>(amask + 4 * (size_t)i);
    uint4 mj = *reinterpret_cast<const uint4*>(amask + 4 * (size_t)j);

#define ALT(A, MI, MJ)                                                       \
    if ((MI) && (MJ)) {                                                      \
        atomicAdd(atomE + 4 * (size_t)i + (A), net);                         \
        atomicAdd(atomE + 4 * (size_t)j + (A), net);                         \
        atomicAdd(resi  + 4 * (size_t)flat_i + (A), net);                    \
        atomicAdd(resi  + 4 * (size_t)flat_j + (A), net);                    \
    }
    ALT(0, mi.x, mj.x)
    ALT(1, mi.y, mj.y)
    ALT(2, mi.z, mj.z)
    ALT(3, mi.w, mj.w)
#undef ALT
}

// ---------------------------------------------------------------------------
// Kernel 2: pair sweep. SG bitmask in shared memory (62.5 KB).
// 8 pairs per thread-iteration: 4x int4 loads issued back-to-back (deep MLP),
// 16 smem bit lookups, 2x float4 streaming stores.
// ---------------------------------------------------------------------------
__global__ void __launch_bounds__(384, 3)
pair_kernel(const int4* __restrict__ pairs2,
            const float* __restrict__ coords,
            const int4* __restrict__ desc4,
            const uint32_t* __restrict__ amask,
            float* __restrict__ out,
            int n_pairs, int n_atoms, int resi_floats)
{
    extern __shared__ uint32_t smask[];
    int nwords = (n_atoms + 31) >> 5;
    for (int w = threadIdx.x; w < nwords; w += blockDim.x)
        smask[w] = g_sgmask[w];
    __syncthreads();

    float* resi  = out;
    float* atomE = out + resi_floats;
    float* sout  = atomE + 4 * (size_t)n_atoms;

    int n8 = n_pairs >> 3;                     // groups of 8 pairs
    int stride = gridDim.x * blockDim.x;

    for (int p = blockIdx.x * blockDim.x + threadIdx.x; p < n8; p += stride) {
        // 4 independent 16B loads: 2 KB in flight per warp
        int4 q0 = __ldcs(pairs2 + 4 * p + 0);
        int4 q1 = __ldcs(pairs2 + 4 * p + 1);
        int4 q2 = __ldcs(pairs2 + 4 * p + 2);
        int4 q3 = __ldcs(pairs2 + 4 * p + 3);

#define BIT(idx) (smask[(idx) >> 5] >> ((idx) & 31))
        unsigned s0 = BIT(q0.x) & BIT(q0.y) & 1u;
        unsigned s1 = BIT(q0.z) & BIT(q0.w) & 1u;
        unsigned s2 = BIT(q1.x) & BIT(q1.y) & 1u;
        unsigned s3 = BIT(q1.z) & BIT(q1.w) & 1u;
        unsigned s4 = BIT(q2.x) & BIT(q2.y) & 1u;
        unsigned s5 = BIT(q2.z) & BIT(q2.w) & 1u;
        unsigned s6 = BIT(q3.x) & BIT(q3.y) & 1u;
        unsigned s7 = BIT(q3.z) & BIT(q3.w) & 1u;
#undef BIT

        float4 soA, soB;
        soA.x = s0 ? 1.0f : 0.0f;
        soA.y = s1 ? 1.0f : 0.0f;
        soA.z = s2 ? 1.0f : 0.0f;
        soA.w = s3 ? 1.0f : 0.0f;
        soB.x = s4 ? 1.0f : 0.0f;
        soB.y = s5 ? 1.0f : 0.0f;
        soB.z = s6 ? 1.0f : 0.0f;
        soB.w = s7 ? 1.0f : 0.0f;
        __stcs(reinterpret_cast<float4*>(sout) + 2 * p + 0, soA);
        __stcs(reinterpret_cast<float4*>(sout) + 2 * p + 1, soB);

        if (s0) heavy_pair(q0.x, q0.y, coords, desc4, amask, atomE, resi);
        if (s1) heavy_pair(q0.z, q0.w, coords, desc4, amask, atomE, resi);
        if (s2) heavy_pair(q1.x, q1.y, coords, desc4, amask, atomE, resi);
        if (s3) heavy_pair(q1.z, q1.w, coords, desc4, amask, atomE, resi);
        if (s4) heavy_pair(q2.x, q2.y, coords, desc4, amask, atomE, resi);
        if (s5) heavy_pair(q2.z, q2.w, coords, desc4, amask, atomE, resi);
        if (s6) heavy_pair(q3.x, q3.y, coords, desc4, amask, atomE, resi);
        if (s7) heavy_pair(q3.z, q3.w, coords, desc4, amask, atomE, resi);
    }

    // tail: n_pairs % 8 (zero here, kept general)
    if (blockIdx.x == 0 && threadIdx.x == 0) {
        const int* pp = reinterpret_cast<const int*>(pairs2);
        for (int q = n8 << 3; q < n_pairs; q++) {
            int i = pp[2 * q], j = pp[2 * q + 1];
            unsigned s = (smask[i >> 5] >> (i & 31))
                       & (smask[j >> 5] >> (j & 31)) & 1u;
            sout[q] = s ? 1.0f : 0.0f;
            if (s) heavy_pair(i, j, coords, desc4, amask, atomE, resi);
        }
    }
}

// ---------------------------------------------------------------------------
extern "C" void kernel_launch(void* const* d_in, const int* in_sizes, int n_in,
                              void* d_out, int out_size)
{
    const float*    coords = (const float*)d_in[0];
    const int*      desc   = (const int*)d_in[1];
    const int*      pairs  = (const int*)d_in[2];
    const uint32_t* amask  = (const uint32_t*)d_in[3];
    float*          out    = (float*)d_out;

    int n_atoms = in_sizes[0] / 3;
    int n_pairs = in_sizes[2] / 2;
    int n_alt   = in_sizes[3] / n_atoms;                      // 4
    int resi_floats = out_size - n_atoms * n_alt - n_pairs;   // 64000

    int nwords = (n_atoms + 31) >> 5;
    size_t smem = (size_t)nwords * 4;                         // 62500 B

    cudaFuncSetAttribute(pair_kernel,
                         cudaFuncAttributeMaxDynamicSharedMemorySize,
                         (int)smem);

    // Zero resi + atom_energy regions (sulfur region fully overwritten).
    cudaMemsetAsync(out, 0,
                    (size_t)(resi_floats + n_atoms * n_alt) * sizeof(float), 0);

    // Mask build: 1024 atoms per 256-thread block, MLP=4.
    int mblocks = (n_atoms + 1023) / 1024;
    mask_kernel<<<mblocks, 256>>>(desc, n_atoms);

    // 3 CTAs/SM (smem-limited), 148 SMs, 384 threads (reg budget for MLP=4).
    pair_kernel<<<444, 384, smem>>>((const int4*)pairs, coords,
                                    (const int4*)desc, amask,
                                    out, n_pairs, n_atoms, resi_floats);
}

// round 6
// speedup vs baseline: 1.2059x; 1.2059x over previous
#include <cuda_runtime.h>
#include <cstdint>

// DisulfideEnergy: sulfur-pair energy scatter + fused residue reduction.
//
// Output (single f32 buffer):
//   [0 .. 64000)              resi_energy (8,4,500,4)
//   [64000 .. 2064000)        atom_energy (500000,4)
//   [2064000 .. 6064000)      sulfur      (4000000) as 0.0/1.0

#define N_CHAINS   4
#define N_RES      500
#define SG_CODE    7
#define MAX_ATOMS  500000
#define MAX_WORDS  ((MAX_ATOMS + 31) / 32)   // 15625

__device__ uint32_t g_sgmask[MAX_WORDS + 32];

// ---------------------------------------------------------------------------
// Kernel 1: build SG bitmask (4 atoms/thread, MLP=4) AND zero the
// resi+atom_energy output regions (replaces the separate memset; this kernel
// is latency-bound with spare DRAM bandwidth).
// ---------------------------------------------------------------------------
__global__ void mask_zero_kernel(const int* __restrict__ desc,
                                 float* __restrict__ out,
                                 int n_atoms, int zero_float4s)
{
    int base = blockIdx.x * 1024;
    int an[4];
#pragma unroll
    for (int u = 0; u < 4; u++) {
        int a = base + u * 256 + threadIdx.x;
        an[u] = (a < n_atoms) ? __ldcs(desc + 4 * a) : 0;   // at_name column
    }
#pragma unroll
    for (int u = 0; u < 4; u++) {
        int a = base + u * 256 + threadIdx.x;
        unsigned ball = __ballot_sync(0xffffffffu, an[u] == SG_CODE);
        if ((threadIdx.x & 31) == 0 && a < n_atoms)
            g_sgmask[a >> 5] = ball;
    }

    // zero resi + atom_energy regions (grid-stride, float4)
    float4 z = make_float4(0.f, 0.f, 0.f, 0.f);
    int stride = gridDim.x * blockDim.x;
    for (int t = blockIdx.x * blockDim.x + threadIdx.x;
         t < zero_float4s; t += stride)
        __stcs(reinterpret_cast<float4*>(out) + t, z);
}

// ---------------------------------------------------------------------------
// Heavy path: only true sulfur pairs (~1/1600). Updates atomE AND resi.
// ---------------------------------------------------------------------------
__device__ __forceinline__ void heavy_pair(int i, int j,
                                           const float* __restrict__ coords,
                                           const int4* __restrict__ desc4,
                                           const uint32_t* __restrict__ amask,
                                           float* __restrict__ atomE,
                                           float* __restrict__ resi)
{
    float dx = __ldg(coords + 3 * i + 0) - __ldg(coords + 3 * j + 0) + 1e-6f;
    float dy = __ldg(coords + 3 * i + 1) - __ldg(coords + 3 * j + 1) + 1e-6f;
    float dz = __ldg(coords + 3 * i + 2) - __ldg(coords + 3 * j + 2) + 1e-6f;
    float dist = sqrtf(dx * dx + dy * dy + dz * dz);

    int4 di = __ldg(desc4 + i);   // (at_name, resnum, batch, chain)
    int4 dj = __ldg(desc4 + j);

    float rd  = fabsf((float)(di.y - dj.y));
    float rds = (rd > 0.f) ? rd : 1.0f;

    // -0.001*298.0 = -0.298
    float energy = -0.298f * (2.1f + 2.9823825f * logf(rds))
                 + 5.0f * fabsf(dist - 2.04f);
    float net = 0.5f * energy;

    int flat_i = (di.z * N_CHAINS + di.w) * N_RES + di.y;
    int flat_j = (dj.z * N_CHAINS + dj.w) * N_RES + dj.y;

    uint4 mi = *reinterpret_cast<const uint4*>(amask + 4 * (size_t)i);
    uint4 mj = *reinterpret_cast<const uint4*>(amask + 4 * (size_t)j);

#define ALT(A, MI, MJ)                                                       \
    if ((MI) && (MJ)) {                                                      \
        atomicAdd(atomE + 4 * (size_t)i + (A), net);                         \
        atomicAdd(atomE + 4 * (size_t)j + (A), net);                         \
        atomicAdd(resi  + 4 * (size_t)flat_i + (A), net);                    \
        atomicAdd(resi  + 4 * (size_t)flat_j + (A), net);                    \
    }
    ALT(0, mi.x, mj.x)
    ALT(1, mi.y, mj.y)
    ALT(2, mi.z, mj.z)
    ALT(3, mi.w, mj.w)
#undef ALT
}

// ---------------------------------------------------------------------------
// Kernel 2: pair sweep. SG bitmask in shared memory (62.5 KB).
// 4 pairs/thread-iter, software-pipelined pair loads (prefetch next iter),
// and short-circuited 2nd bit lookup (predicated LDS, ~1 phase vs ~4).
// ---------------------------------------------------------------------------
__global__ void __launch_bounds__(512, 3)
pair_kernel(const int4* __restrict__ pairs2,
            const float* __restrict__ coords,
            const int4* __restrict__ desc4,
            const uint32_t* __restrict__ amask,
            float* __restrict__ out,
            int n_pairs, int n_atoms, int resi_floats)
{
    extern __shared__ uint32_t smask[];
    int nwords = (n_atoms + 31) >> 5;
    for (int w = threadIdx.x; w < nwords; w += blockDim.x)
        smask[w] = g_sgmask[w];
    __syncthreads();

    float* resi  = out;
    float* atomE = out + resi_floats;
    float* sout  = atomE + 4 * (size_t)n_atoms;

    int n4 = n_pairs >> 2;                     // groups of 4 pairs
    int stride = gridDim.x * blockDim.x;

    int idx = blockIdx.x * blockDim.x + threadIdx.x;
    int4 a0, a1;
    bool valid = idx < n4;
    if (valid) {
        a0 = __ldcs(pairs2 + 2 * idx);
        a1 = __ldcs(pairs2 + 2 * idx + 1);
    }

    while (valid) {
        // prefetch next iteration's pairs (hides DRAM latency)
        int nidx = idx + stride;
        bool nvalid = nidx < n4;
        int4 b0, b1;
        if (nvalid) {
            b0 = __ldcs(pairs2 + 2 * nidx);
            b1 = __ldcs(pairs2 + 2 * nidx + 1);
        }

        // first lookups (unconditional), second lookups predicated on first
#define BIT1(idx_) ((smask[(idx_) >> 5] >> ((idx_) & 31)) & 1u)
        unsigned s0 = BIT1(a0.x); if (s0) s0 = BIT1(a0.y);
        unsigned s1 = BIT1(a0.z); if (s1) s1 = BIT1(a0.w);
        unsigned s2 = BIT1(a1.x); if (s2) s2 = BIT1(a1.y);
        unsigned s3 = BIT1(a1.z); if (s3) s3 = BIT1(a1.w);
#undef BIT1

        float4 so;
        so.x = s0 ? 1.0f : 0.0f;
        so.y = s1 ? 1.0f : 0.0f;
        so.z = s2 ? 1.0f : 0.0f;
        so.w = s3 ? 1.0f : 0.0f;
        __stcs(reinterpret_cast<float4*>(sout) + idx, so);

        if (s0) heavy_pair(a0.x, a0.y, coords, desc4, amask, atomE, resi);
        if (s1) heavy_pair(a0.z, a0.w, coords, desc4, amask, atomE, resi);
        if (s2) heavy_pair(a1.x, a1.y, coords, desc4, amask, atomE, resi);
        if (s3) heavy_pair(a1.z, a1.w, coords, desc4, amask, atomE, resi);

        a0 = b0; a1 = b1; idx = nidx; valid = nvalid;
    }

    // tail: n_pairs % 4 (zero here, kept general)
    if (blockIdx.x == 0 && threadIdx.x == 0) {
        const int* pp = reinterpret_cast<const int*>(pairs2);
        for (int q = n4 << 2; q < n_pairs; q++) {
            int i = pp[2 * q], j = pp[2 * q + 1];
            unsigned s = (smask[i >> 5] >> (i & 31))
                       & (smask[j >> 5] >> (j & 31)) & 1u;
            sout[q] = s ? 1.0f : 0.0f;
            if (s) heavy_pair(i, j, coords, desc4, amask, atomE, resi);
        }
    }
}

// ---------------------------------------------------------------------------
extern "C" void kernel_launch(void* const* d_in, const int* in_sizes, int n_in,
                              void* d_out, int out_size)
{
    const float*    coords = (const float*)d_in[0];
    const int*      desc   = (const int*)d_in[1];
    const int*      pairs  = (const int*)d_in[2];
    const uint32_t* amask  = (const uint32_t*)d_in[3];
    float*          out    = (float*)d_out;

    int n_atoms = in_sizes[0] / 3;
    int n_pairs = in_sizes[2] / 2;
    int n_alt   = in_sizes[3] / n_atoms;                      // 4
    int resi_floats = out_size - n_atoms * n_alt - n_pairs;   // 64000

    int nwords = (n_atoms + 31) >> 5;
    size_t smem = (size_t)nwords * 4;                         // 62500 B

    cudaFuncSetAttribute(pair_kernel,
                         cudaFuncAttributeMaxDynamicSharedMemorySize,
                         (int)smem);

    // Mask build + zero resi/atomE regions in one kernel.
    int mblocks = (n_atoms + 1023) / 1024;
    int zero_float4s = (resi_floats + n_atoms * n_alt) / 4;
    mask_zero_kernel<<<mblocks, 256>>>(desc, out, n_atoms, zero_float4s);

    // 3 CTAs/SM (smem-limited), 148 SMs, 512 threads (best measured occ).
    pair_kernel<<<444, 512, smem>>>((const int4*)pairs, coords,
                                    (const int4*)desc, amask,
                                    out, n_pairs, n_atoms, resi_floats);
}

// round 7
// speedup vs baseline: 1.3374x; 1.1090x over previous
#include <cuda_runtime.h>
#include <cstdint>

// DisulfideEnergy: sulfur-pair energy scatter + fused residue reduction.
//
// Output (single f32 buffer):
//   [0 .. 64000)              resi_energy (8,4,500,4)
//   [64000 .. 2064000)        atom_energy (500000,4)
//   [2064000 .. 6064000)      sulfur      (4000000) as 0.0/1.0

#define N_CHAINS   4
#define N_RES      500
#define SG_CODE    7
#define MAX_ATOMS  500000
#define MAX_WORDS  ((MAX_ATOMS + 31) / 32)   // 15625

__device__ __align__(16) uint32_t g_sgmask[MAX_WORDS + 32];

// ---------------------------------------------------------------------------
// Kernel 1: build SG bitmask (4 atoms/thread, MLP=4) AND zero the
// resi+atom_energy output regions.
// ---------------------------------------------------------------------------
__global__ void mask_zero_kernel(const int* __restrict__ desc,
                                 float* __restrict__ out,
                                 int n_atoms, int zero_float4s)
{
    int base = blockIdx.x * 1024;
    int an[4];
#pragma unroll
    for (int u = 0; u < 4; u++) {
        int a = base + u * 256 + threadIdx.x;
        an[u] = (a < n_atoms) ? __ldcs(desc + 4 * a) : 0;   // at_name column
    }
#pragma unroll
    for (int u = 0; u < 4; u++) {
        int a = base + u * 256 + threadIdx.x;
        unsigned ball = __ballot_sync(0xffffffffu, an[u] == SG_CODE);
        if ((threadIdx.x & 31) == 0 && a < n_atoms)
            g_sgmask[a >> 5] = ball;
    }

    // zero resi + atom_energy regions (grid-stride, float4)
    float4 z = make_float4(0.f, 0.f, 0.f, 0.f);
    int stride = gridDim.x * blockDim.x;
    for (int t = blockIdx.x * blockDim.x + threadIdx.x;
         t < zero_float4s; t += stride)
        __stcs(reinterpret_cast<float4*>(out) + t, z);
}

// ---------------------------------------------------------------------------
// Heavy path: only true sulfur pairs (~1/1600). Updates atomE AND resi.
// Marked noinline so its register demand doesn't inflate the hot loop.
// ---------------------------------------------------------------------------
__device__ __noinline__ void heavy_pair(int i, int j,
                                        const float* __restrict__ coords,
                                        const int4* __restrict__ desc4,
                                        const uint32_t* __restrict__ amask,
                                        float* __restrict__ atomE,
                                        float* __restrict__ resi)
{
    float dx = __ldg(coords + 3 * i + 0) - __ldg(coords + 3 * j + 0) + 1e-6f;
    float dy = __ldg(coords + 3 * i + 1) - __ldg(coords + 3 * j + 1) + 1e-6f;
    float dz = __ldg(coords + 3 * i + 2) - __ldg(coords + 3 * j + 2) + 1e-6f;
    float dist = sqrtf(dx * dx + dy * dy + dz * dz);

    int4 di = __ldg(desc4 + i);   // (at_name, resnum, batch, chain)
    int4 dj = __ldg(desc4 + j);

    float rd  = fabsf((float)(di.y - dj.y));
    float rds = (rd > 0.f) ? rd : 1.0f;

    // -0.001*298.0 = -0.298
    float energy = -0.298f * (2.1f + 2.9823825f * logf(rds))
                 + 5.0f * fabsf(dist - 2.04f);
    float net = 0.5f * energy;

    int flat_i = (di.z * N_CHAINS + di.w) * N_RES + di.y;
    int flat_j = (dj.z * N_CHAINS + dj.w) * N_RES + dj.y;

    uint4 mi = *reinterpret_cast<const uint4*>(amask + 4 * (size_t)i);
    uint4 mj = *reinterpret_cast<const uint4*>(amask + 4 * (size_t)j);

#define ALT(A, MI, MJ)                                                       \
    if ((MI) && (MJ)) {                                                      \
        atomicAdd(atomE + 4 * (size_t)i + (A), net);                         \
        atomicAdd(atomE + 4 * (size_t)j + (A), net);                         \
        atomicAdd(resi  + 4 * (size_t)flat_i + (A), net);                    \
        atomicAdd(resi  + 4 * (size_t)flat_j + (A), net);                    \
    }
    ALT(0, mi.x, mj.x)
    ALT(1, mi.y, mj.y)
    ALT(2, mi.z, mj.z)
    ALT(3, mi.w, mj.w)
#undef ALT
}

// ---------------------------------------------------------------------------
// Kernel 2: pair sweep. SG bitmask in shared memory (62.5 KB).
// 1024 threads x 2 CTAs/SM = 64 warps/SM (reg-capped at 32/thread).
// 2 pairs/thread-iter, 1-deep prefetch: 2048 thr x 16B = 32 KB in flight/SM.
// ---------------------------------------------------------------------------
__global__ void __launch_bounds__(1024, 2)
pair_kernel(const int4* __restrict__ pairs2,
            const float* __restrict__ coords,
            const int4* __restrict__ desc4,
            const uint32_t* __restrict__ amask,
            float* __restrict__ out,
            int n_pairs, int n_atoms, int resi_floats)
{
    extern __shared__ __align__(16) uint32_t smask[];
    int nwords = (n_atoms + 31) >> 5;
    int nw4 = nwords >> 2;
    {
        const uint4* gm4 = reinterpret_cast<const uint4*>(g_sgmask);
        uint4* sm4 = reinterpret_cast<uint4*>(smask);
        for (int w = threadIdx.x; w < nw4; w += blockDim.x)
            sm4[w] = gm4[w];
        for (int w = (nw4 << 2) + threadIdx.x; w < nwords; w += blockDim.x)
            smask[w] = g_sgmask[w];
    }
    __syncthreads();

    float* resi  = out;
    float* atomE = out + resi_floats;
    float* sout  = atomE + 4 * (size_t)n_atoms;

    int n2 = n_pairs >> 1;                     // groups of 2 pairs
    int stride = gridDim.x * blockDim.x;

    int idx = blockIdx.x * blockDim.x + threadIdx.x;
    int4 a;
    bool valid = idx < n2;
    if (valid) a = __ldcs(pairs2 + idx);

    while (valid) {
        // prefetch next iteration's pairs (hides DRAM latency)
        int nidx = idx + stride;
        bool nvalid = nidx < n2;
        int4 b;
        if (nvalid) b = __ldcs(pairs2 + nidx);

        // first lookup unconditional, second predicated (p ~ 1/40)
#define BIT1(I) ((smask[(unsigned)(I) >> 5] >> ((I) & 31)) & 1u)
        unsigned s0 = BIT1(a.x); if (s0) s0 = BIT1(a.y);
        unsigned s1 = BIT1(a.z); if (s1) s1 = BIT1(a.w);
#undef BIT1

        float2 so;
        so.x = s0 ? 1.0f : 0.0f;
        so.y = s1 ? 1.0f : 0.0f;
        __stcs(reinterpret_cast<float2*>(sout) + idx, so);

        if (s0) heavy_pair(a.x, a.y, coords, desc4, amask, atomE, resi);
        if (s1) heavy_pair(a.z, a.w, coords, desc4, amask, atomE, resi);

        a = b; idx = nidx; valid = nvalid;
    }

    // tail: odd pair (zero here, kept general)
    if ((n_pairs & 1) && blockIdx.x == 0 && threadIdx.x == 0) {
        const int* pp = reinterpret_cast<const int*>(pairs2);
        int i = pp[2 * (n_pairs - 1)], j = pp[2 * (n_pairs - 1) + 1];
        unsigned s = (smask[i >> 5] >> (i & 31))
                   & (smask[j >> 5] >> (j & 31)) & 1u;
        sout[n_pairs - 1] = s ? 1.0f : 0.0f;
        if (s) heavy_pair(i, j, coords, desc4, amask, atomE, resi);
    }
}

// ---------------------------------------------------------------------------
extern "C" void kernel_launch(void* const* d_in, const int* in_sizes, int n_in,
                              void* d_out, int out_size)
{
    const float*    coords = (const float*)d_in[0];
    const int*      desc   = (const int*)d_in[1];
    const int*      pairs  = (const int*)d_in[2];
    const uint32_t* amask  = (const uint32_t*)d_in[3];
    float*          out    = (float*)d_out;

    int n_atoms = in_sizes[0] / 3;
    int n_pairs = in_sizes[2] / 2;
    int n_alt   = in_sizes[3] / n_atoms;                      // 4
    int resi_floats = out_size - n_atoms * n_alt - n_pairs;   // 64000

    int nwords = (n_atoms + 31) >> 5;
    size_t smem = (size_t)nwords * 4;                         // 62500 B

    cudaFuncSetAttribute(pair_kernel,
                         cudaFuncAttributeMaxDynamicSharedMemorySize,
                         (int)smem);

    // Mask build + zero resi/atomE regions in one kernel.
    int mblocks = (n_atoms + 1023) / 1024;
    int zero_float4s = (resi_floats + n_atoms * n_alt) / 4;
    mask_zero_kernel<<<mblocks, 256>>>(desc, out, n_atoms, zero_float4s);

    // 2 CTAs/SM x 1024 threads = 64 warps/SM (full occupancy).
    pair_kernel<<<296, 1024, smem>>>((const int4*)pairs, coords,
                                     (const int4*)desc, amask,
                                     out, n_pairs, n_atoms, resi_floats);
}